// round 1
// baseline (speedup 1.0000x reference)
#include <cuda_runtime.h>
#include <math.h>

#define RT     128     // rows per block
#define PITCH  132     // smem row pitch in floats (float4-aligned, conflict-friendly)
#define NT     256     // threads per block

struct Params {
  const int*   obs;
  const float *embed, *W1, *b1, *W2, *b2, *W3, *b3, *Wp, *bp, *codebook;
  const float *Wa, *ba, *Ws, *bs, *Wc1, *bc1, *Wc2, *bc2, *Wc3, *bc3, *Wc4, *bc4;
  float *out_actor, *out_scale, *out_critic, *out_loss, *out_idx;
};

struct SmemT {
  float bufA[RT * PITCH];     // 67584 B
  float bufB[RT * PITCH];     // 67584 B
  float wbuf[128 * 128];      // 65536 B (weights / codebook chunk)
  float bias[128];
  float cnorm[256];
  float bestd[2][RT];
  int   bestidx[2][RT];
  int   idxs[RT];
  float red[8];
};                            // ~204.8 KB total

__device__ float g_partials[1024];

__device__ __forceinline__ float sigf(float x) { return 1.0f / (1.0f + expf(-x)); }

__device__ __forceinline__ void load_w(float* dst, const float* src, int nfloats) {
  const int tid = threadIdx.x;
  const int n4 = nfloats >> 2;
  for (int i = tid; i < n4; i += NT)
    reinterpret_cast<float4*>(dst)[i] = reinterpret_cast<const float4*>(src)[i];
}
__device__ __forceinline__ void load_b(float* dst, const float* src, int n) {
  const int tid = threadIdx.x;
  for (int i = tid; i < n; i += NT) dst[i] = src[i];
}

// ACT: 0 = linear, 1 = relu, 2 = sigmoid, 3 = sigmoid + 1e-8
template<int K, int N, int ACT>
__device__ __forceinline__ void gemm_stage(
    const float* __restrict__ in_s, const float* __restrict__ w_s,
    const float* __restrict__ b_s, float* out_s, float* out_g, int row0)
{
  constexpr int TN = N / 16;
  const int tid = threadIdx.x;
  const int tx = tid & 15, ty = tid >> 4;   // 16 x 16 thread grid; each: 8 rows x TN cols
  float acc[8][TN];
  #pragma unroll
  for (int i = 0; i < 8; i++)
    #pragma unroll
    for (int j = 0; j < TN; j++) acc[i][j] = 0.f;

  const float* ap = in_s + ty * 8 * PITCH;
  const float* wp = w_s + tx * TN;

  #pragma unroll 4
  for (int k = 0; k < K; k++) {
    float a[8];
    #pragma unroll
    for (int i = 0; i < 8; i++) a[i] = ap[i * PITCH + k];   // warp-broadcast reads
    float b[TN];
    #pragma unroll
    for (int j = 0; j < TN; j++) b[j] = wp[k * N + j];      // contiguous, vectorizable
    #pragma unroll
    for (int i = 0; i < 8; i++)
      #pragma unroll
      for (int j = 0; j < TN; j++) acc[i][j] = fmaf(a[i], b[j], acc[i][j]);
  }

  float bv[TN];
  #pragma unroll
  for (int j = 0; j < TN; j++) bv[j] = b_s[tx * TN + j];

  #pragma unroll
  for (int i = 0; i < 8; i++) {
    const int r = ty * 8 + i;
    #pragma unroll
    for (int j = 0; j < TN; j++) {
      float v = acc[i][j] + bv[j];
      if (ACT == 1) v = v > 0.f ? v : 0.f;
      if (ACT == 2 || ACT == 3) v = sigf(v);
      if (ACT == 3) v += 1e-8f;
      if (out_s) out_s[r * PITCH + tx * TN + j] = v;
      if (out_g) out_g[(size_t)(row0 + r) * N + tx * TN + j] = v;
    }
  }
}

__global__ void __launch_bounds__(NT, 1) acsq_main(Params p)
{
  extern __shared__ char smraw[];
  SmemT& sm = *reinterpret_cast<SmemT*>(smraw);
  const int tid = threadIdx.x;
  const int row0 = blockIdx.x * RT;

  // ---- embedding gather: bufA[r][0:128] = embed[obs[row0+r]] ----
  for (int i = tid; i < RT * 32; i += NT) {
    const int r = i >> 5, c = i & 31;
    const int o = p.obs[row0 + r];
    reinterpret_cast<float4*>(sm.bufA + r * PITCH)[c] =
        reinterpret_cast<const float4*>(p.embed + (size_t)o * 128)[c];
  }

  // ---- MLP stack ----
  load_w(sm.wbuf, p.W1, 128 * 128); load_b(sm.bias, p.b1, 128);
  __syncthreads();
  gemm_stage<128, 128, 1>(sm.bufA, sm.wbuf, sm.bias, sm.bufB, nullptr, row0);
  __syncthreads();
  load_w(sm.wbuf, p.W2, 128 * 128); load_b(sm.bias, p.b2, 128);
  __syncthreads();
  gemm_stage<128, 128, 1>(sm.bufB, sm.wbuf, sm.bias, sm.bufA, nullptr, row0);
  __syncthreads();
  load_w(sm.wbuf, p.W3, 128 * 128); load_b(sm.bias, p.b3, 128);
  __syncthreads();
  gemm_stage<128, 128, 1>(sm.bufA, sm.wbuf, sm.bias, sm.bufB, nullptr, row0);
  __syncthreads();
  load_w(sm.wbuf, p.Wp, 128 * 64);  load_b(sm.bias, p.bp, 64);
  __syncthreads();
  gemm_stage<128, 64, 0>(sm.bufB, sm.wbuf, sm.bias, sm.bufA, nullptr, row0);
  __syncthreads();
  // z in bufA[:, 0:64]

  // ---- VQ: argmin over 512 codes (2 smem chunks x 2 warp-halves) ----
  const int warp = tid >> 5, lane = tid & 31;
  const int myrow = (warp & 3) * 32 + lane;
  const int half = warp >> 2;

  float z[64];
  #pragma unroll
  for (int k = 0; k < 64; k++) z[k] = sm.bufA[myrow * PITCH + k];
  float znorm = 0.f;
  #pragma unroll
  for (int k = 0; k < 64; k++) znorm = fmaf(z[k], z[k], znorm);

  float best = 3.4e38f;
  int bidx = 0;
  for (int chunk = 0; chunk < 2; chunk++) {
    __syncthreads();   // previous wbuf users done
    {
      const float* cbg = p.codebook + (size_t)chunk * 256 * 64;
      for (int i = tid; i < 256 * 64 / 4; i += NT)
        reinterpret_cast<float4*>(sm.wbuf)[i] = reinterpret_cast<const float4*>(cbg)[i];
    }
    __syncthreads();
    {  // per-code squared norms (matches reference sum(cb*cb, axis=1))
      float s = 0.f;
      const float* cr = sm.wbuf + tid * 64;
      #pragma unroll 8
      for (int k = 0; k < 64; k++) s = fmaf(cr[k], cr[k], s);
      sm.cnorm[tid] = s;
    }
    __syncthreads();
    const int cbase = half * 128;
    for (int cc = 0; cc < 128; cc++) {
      const int c = cbase + cc;
      const float4* c4 = reinterpret_cast<const float4*>(sm.wbuf + c * 64);
      float dot = 0.f;
      #pragma unroll
      for (int q = 0; q < 16; q++) {
        const float4 v = c4[q];  // broadcast across warp
        dot = fmaf(z[4 * q + 0], v.x, dot);
        dot = fmaf(z[4 * q + 1], v.y, dot);
        dot = fmaf(z[4 * q + 2], v.z, dot);
        dot = fmaf(z[4 * q + 3], v.w, dot);
      }
      const float d = znorm - 2.f * dot + sm.cnorm[c];
      const int gc = chunk * 256 + c;
      if (d < best) { best = d; bidx = gc; }   // first-min tie-break (ascending scan)
    }
  }
  __syncthreads();
  sm.bestd[half][myrow] = best;
  sm.bestidx[half][myrow] = bidx;
  __syncthreads();
  if (warp < 4) {
    const float d0 = sm.bestd[0][myrow], d1 = sm.bestd[1][myrow];
    const int i0 = sm.bestidx[0][myrow], i1 = sm.bestidx[1][myrow];
    const int fi = (d1 < d0 || (d1 == d0 && i1 < i0)) ? i1 : i0;
    sm.idxs[myrow] = fi;
    p.out_idx[row0 + myrow] = (float)fi;
  }
  __syncthreads();

  // ---- quant gather into bufB[:, 0:64] ----
  for (int i = tid; i < RT * 16; i += NT) {
    const int r = i >> 4, c = i & 15;
    reinterpret_cast<float4*>(sm.bufB + r * PITCH)[c] =
        reinterpret_cast<const float4*>(p.codebook + (size_t)sm.idxs[r] * 64)[c];
  }
  __syncthreads();

  // ---- vq_loss partial: sum((quant - z)^2), deterministic ----
  float ls = 0.f;
  for (int i = tid; i < RT * 64; i += NT) {
    const int r = i >> 6, k = i & 63;
    const float dd = sm.bufB[r * PITCH + k] - sm.bufA[r * PITCH + k];
    ls = fmaf(dd, dd, ls);
  }
  #pragma unroll
  for (int o = 16; o; o >>= 1) ls += __shfl_down_sync(0xffffffffu, ls, o);
  if (lane == 0) sm.red[warp] = ls;
  __syncthreads();
  if (tid == 0) {
    float t = 0.f;
    for (int w = 0; w < 8; w++) t += sm.red[w];
    g_partials[blockIdx.x] = t;
  }
  __syncthreads();

  // ---- heads (input = quant in bufB) ----
  load_w(sm.wbuf, p.Wa, 64 * 128); load_b(sm.bias, p.ba, 128);
  __syncthreads();
  gemm_stage<64, 128, 2>(sm.bufB, sm.wbuf, sm.bias, nullptr, p.out_actor, row0);
  __syncthreads();
  load_w(sm.wbuf, p.Ws, 64 * 128); load_b(sm.bias, p.bs, 128);
  __syncthreads();
  gemm_stage<64, 128, 3>(sm.bufB, sm.wbuf, sm.bias, nullptr, p.out_scale, row0);
  __syncthreads();
  load_w(sm.wbuf, p.Wc1, 64 * 128); load_b(sm.bias, p.bc1, 128);
  __syncthreads();
  gemm_stage<64, 128, 2>(sm.bufB, sm.wbuf, sm.bias, sm.bufA, nullptr, row0);
  __syncthreads();
  load_w(sm.wbuf, p.Wc2, 128 * 128); load_b(sm.bias, p.bc2, 128);
  __syncthreads();
  gemm_stage<128, 128, 2>(sm.bufA, sm.wbuf, sm.bias, sm.bufB, nullptr, row0);
  __syncthreads();
  load_w(sm.wbuf, p.Wc3, 128 * 32); load_b(sm.bias, p.bc3, 32);
  __syncthreads();
  gemm_stage<128, 32, 2>(sm.bufB, sm.wbuf, sm.bias, sm.bufA, nullptr, row0);
  __syncthreads();
  load_b(sm.bias, p.Wc4, 32);
  if (tid == 0) sm.bias[32] = *p.bc4;
  __syncthreads();
  if (tid < RT) {
    float s = sm.bias[32];
    const float* cr = sm.bufA + tid * PITCH;
    #pragma unroll
    for (int k = 0; k < 32; k++) s = fmaf(cr[k], sm.bias[k], s);
    p.out_critic[row0 + tid] = s;
  }
}

__global__ void acsq_reduce(float* out_loss, int nblocks, float scale)
{
  __shared__ float s[NT];
  float v = 0.f;
  for (int i = threadIdx.x; i < nblocks; i += NT) v += g_partials[i];  // fixed order
  s[threadIdx.x] = v;
  __syncthreads();
  for (int o = NT / 2; o > 0; o >>= 1) {
    if (threadIdx.x < o) s[threadIdx.x] += s[threadIdx.x + o];
    __syncthreads();
  }
  if (threadIdx.x == 0) *out_loss = s[0] * scale;
}

extern "C" void kernel_launch(void* const* d_in, const int* in_sizes, int n_in,
                              void* d_out, int out_size)
{
  Params p;
  p.obs      = (const int*)d_in[0];
  p.embed    = (const float*)d_in[1];
  p.W1  = (const float*)d_in[2];  p.b1  = (const float*)d_in[3];
  p.W2  = (const float*)d_in[4];  p.b2  = (const float*)d_in[5];
  p.W3  = (const float*)d_in[6];  p.b3  = (const float*)d_in[7];
  p.Wp  = (const float*)d_in[8];  p.bp  = (const float*)d_in[9];
  p.codebook = (const float*)d_in[10];
  p.Wa  = (const float*)d_in[11]; p.ba  = (const float*)d_in[12];
  p.Ws  = (const float*)d_in[13]; p.bs  = (const float*)d_in[14];
  p.Wc1 = (const float*)d_in[15]; p.bc1 = (const float*)d_in[16];
  p.Wc2 = (const float*)d_in[17]; p.bc2 = (const float*)d_in[18];
  p.Wc3 = (const float*)d_in[19]; p.bc3 = (const float*)d_in[20];
  p.Wc4 = (const float*)d_in[21]; p.bc4 = (const float*)d_in[22];

  const int B = in_sizes[0];
  float* out = (float*)d_out;
  p.out_actor  = out;                                  // [B,128]
  p.out_scale  = out + (size_t)B * 128;                // [B,128]
  p.out_critic = out + (size_t)2 * B * 128;            // [B]
  p.out_loss   = out + (size_t)2 * B * 128 + B;        // scalar
  p.out_idx    = out + (size_t)2 * B * 128 + B + 1;    // [B] as float

  cudaFuncSetAttribute(acsq_main, cudaFuncAttributeMaxDynamicSharedMemorySize,
                       (int)sizeof(SmemT));
  acsq_main<<<B / RT, NT, sizeof(SmemT)>>>(p);
  acsq_reduce<<<1, NT>>>(p.out_loss, B / RT, 1.25f / ((float)B * 64.f));
}

// round 2
// speedup vs baseline: 12.3041x; 12.3041x over previous
#include <cuda_runtime.h>
#include <math.h>

#define NT 256

struct Params {
  const int*   obs;
  const float *embed, *W1, *b1, *W2, *b2, *W3, *b3, *Wp, *bp, *codebook;
  const float *Wa, *ba, *Ws, *bs, *Wc1, *bc1, *Wc2, *bc2, *Wc3, *bc3, *Wc4, *bc4;
  float *out_actor, *out_scale, *out_critic, *out_loss, *out_idx;
  int NC, VQN, nClsBlk, B;
};

// Device-global scratch (no allocation allowed)
__device__ int   g_idx_cls[1024];
__device__ float g_loss_cls[1024];
__device__ float g_tbl_actor[512 * 128];
__device__ float g_tbl_scale[512 * 128];
__device__ float g_tbl_crit[512];
__device__ float g_partials[1024];

struct SmemAB {
  float wbuf[128 * 128];   // 64 KB: one weight matrix (or chunk)
  float bias[128];
  float A[8][128];
  float Bb[8][128];
  float znorm[8];
  float dist[8][512];      // 16 KB: per-row code distances
};

__device__ __forceinline__ float sigf(float x) { return 1.0f / (1.0f + expf(-x)); }

__device__ __forceinline__ void stage_w(float* dst, const float* src, int nfloats) {
  const int n4 = nfloats >> 2;
  for (int i = threadIdx.x; i < n4; i += NT)
    reinterpret_cast<float4*>(dst)[i] = reinterpret_cast<const float4*>(src)[i];
}
__device__ __forceinline__ void stage_b(float* dst, const float* src, int n) {
  for (int i = threadIdx.x; i < n; i += NT) dst[i] = src[i];
}

// 8-row GEMM layer: out[r][n] = act( sum_k in[r][k] * W[k][n] + b[n] )
// Thread r = tid>>5 (8 rows), lane covers float4 column groups.
// ACT: 0 linear, 1 relu, 2 sigmoid, 3 sigmoid + 1e-8
template<int K, int N, int ACT>
__device__ __forceinline__ void layer8(const float (*__restrict__ in)[128],
                                       const float* __restrict__ wb,
                                       const float* __restrict__ bs,
                                       float (*__restrict__ outs)[128],
                                       float* __restrict__ outg, int grow0)
{
  const int tid  = threadIdx.x;
  const int r    = tid >> 5;
  const int lane = tid & 31;
  const float4* w4base = reinterpret_cast<const float4*>(wb);

  for (int c4 = lane; c4 < N / 4; c4 += 32) {
    float4 acc = make_float4(0.f, 0.f, 0.f, 0.f);
    const float4* w4 = w4base + c4;
    #pragma unroll 4
    for (int k = 0; k < K; k++) {
      const float  a = in[r][k];                 // warp-broadcast
      const float4 w = w4[k * (N / 4)];
      acc.x = fmaf(a, w.x, acc.x);
      acc.y = fmaf(a, w.y, acc.y);
      acc.z = fmaf(a, w.z, acc.z);
      acc.w = fmaf(a, w.w, acc.w);
    }
    const float4 bb = reinterpret_cast<const float4*>(bs)[c4];
    float v[4] = {acc.x + bb.x, acc.y + bb.y, acc.z + bb.z, acc.w + bb.w};
    #pragma unroll
    for (int j = 0; j < 4; j++) {
      if (ACT == 1) v[j] = v[j] > 0.f ? v[j] : 0.f;
      if (ACT == 2 || ACT == 3) v[j] = sigf(v[j]);
      if (ACT == 3) v[j] += 1e-8f;
    }
    const float4 vv = make_float4(v[0], v[1], v[2], v[3]);
    if (outs) *reinterpret_cast<float4*>(&outs[r][c4 * 4]) = vv;
    if (outg)
      reinterpret_cast<float4*>(outg)[(size_t)(grow0 + r) * (N / 4) + c4] = vv;
  }
}

__global__ void __launch_bounds__(NT, 1) acsq_ab(Params p)
{
  extern __shared__ char smraw[];
  SmemAB& sm = *reinterpret_cast<SmemAB*>(smraw);
  const int tid = threadIdx.x;

  if ((int)blockIdx.x < p.nClsBlk) {
    // ================= CLASS PATH: front MLP + VQ for 8 classes =============
    const int c0 = blockIdx.x * 8;

    for (int i = tid; i < 8 * 32; i += NT) {          // embed gather
      const int r = i >> 5, col = i & 31, cls = c0 + r;
      float4 v = make_float4(0.f, 0.f, 0.f, 0.f);
      if (cls < p.NC)
        v = reinterpret_cast<const float4*>(p.embed + (size_t)cls * 128)[col];
      reinterpret_cast<float4*>(sm.A[r])[col] = v;
    }
    stage_w(sm.wbuf, p.W1, 128 * 128); stage_b(sm.bias, p.b1, 128);
    __syncthreads();
    layer8<128, 128, 1>(sm.A, sm.wbuf, sm.bias, sm.Bb, nullptr, 0);
    __syncthreads();
    stage_w(sm.wbuf, p.W2, 128 * 128); stage_b(sm.bias, p.b2, 128);
    __syncthreads();
    layer8<128, 128, 1>(sm.Bb, sm.wbuf, sm.bias, sm.A, nullptr, 0);
    __syncthreads();
    stage_w(sm.wbuf, p.W3, 128 * 128); stage_b(sm.bias, p.b3, 128);
    __syncthreads();
    layer8<128, 128, 1>(sm.A, sm.wbuf, sm.bias, sm.Bb, nullptr, 0);
    __syncthreads();
    stage_w(sm.wbuf, p.Wp, 128 * 64);  stage_b(sm.bias, p.bp, 64);
    __syncthreads();
    layer8<128, 64, 0>(sm.Bb, sm.wbuf, sm.bias, sm.A, nullptr, 0);  // z in A[:,0:64]
    __syncthreads();

    if (tid < 8) {
      float s = 0.f;
      #pragma unroll
      for (int k = 0; k < 64; k++) s = fmaf(sm.A[tid][k], sm.A[tid][k], s);
      sm.znorm[tid] = s;
    }
    __syncthreads();

    for (int cc = tid; cc < p.VQN; cc += NT) {
      float4 cb[16];
      const float4* cp = reinterpret_cast<const float4*>(p.codebook + (size_t)cc * 64);
      #pragma unroll
      for (int q = 0; q < 16; q++) cb[q] = cp[q];
      float cn = 0.f;
      #pragma unroll
      for (int q = 0; q < 16; q++) {
        cn = fmaf(cb[q].x, cb[q].x, cn); cn = fmaf(cb[q].y, cb[q].y, cn);
        cn = fmaf(cb[q].z, cb[q].z, cn); cn = fmaf(cb[q].w, cb[q].w, cn);
      }
      #pragma unroll
      for (int r = 0; r < 8; r++) {
        float dot = 0.f;
        #pragma unroll
        for (int q = 0; q < 16; q++) {
          dot = fmaf(sm.A[r][4 * q + 0], cb[q].x, dot);
          dot = fmaf(sm.A[r][4 * q + 1], cb[q].y, dot);
          dot = fmaf(sm.A[r][4 * q + 2], cb[q].z, dot);
          dot = fmaf(sm.A[r][4 * q + 3], cb[q].w, dot);
        }
        sm.dist[r][cc] = sm.znorm[r] - 2.f * dot + cn;
      }
    }
    __syncthreads();

    const int warp = tid >> 5, lane = tid & 31;
    if (warp < 8) {
      const int r = warp;
      float best = 3.4e38f; int bi = 0;
      for (int cc = lane; cc < p.VQN; cc += 32) {     // ascending per lane
        const float d = sm.dist[r][cc];
        if (d < best) { best = d; bi = cc; }
      }
      #pragma unroll
      for (int o = 16; o; o >>= 1) {                  // lexicographic (d, idx) min
        const float ob = __shfl_down_sync(0xffffffffu, best, o);
        const int   oi = __shfl_down_sync(0xffffffffu, bi,   o);
        if (ob < best || (ob == best && oi < bi)) { best = ob; bi = oi; }
      }
      bi = __shfl_sync(0xffffffffu, bi, 0);
      float ls = 0.f;
      for (int k = lane; k < 64; k += 32) {
        const float dq = p.codebook[(size_t)bi * 64 + k] - sm.A[r][k];
        ls = fmaf(dq, dq, ls);
      }
      #pragma unroll
      for (int o = 16; o; o >>= 1) ls += __shfl_down_sync(0xffffffffu, ls, o);
      if (lane == 0 && c0 + r < p.NC) {
        g_idx_cls[c0 + r]  = bi;
        g_loss_cls[c0 + r] = ls;
      }
    }
  } else {
    // ================= HEAD PATH: head tables for 8 codes ===================
    const int q0 = (blockIdx.x - p.nClsBlk) * 8;

    for (int i = tid; i < 8 * 16; i += NT) {          // gather codebook rows
      const int r = i >> 4, col = i & 15;
      reinterpret_cast<float4*>(sm.A[r])[col] =
          reinterpret_cast<const float4*>(p.codebook + (size_t)(q0 + r) * 64)[col];
    }
    stage_w(sm.wbuf, p.Wa, 64 * 128); stage_b(sm.bias, p.ba, 128);
    __syncthreads();
    layer8<64, 128, 2>(sm.A, sm.wbuf, sm.bias, nullptr, g_tbl_actor, q0);
    __syncthreads();
    stage_w(sm.wbuf, p.Ws, 64 * 128); stage_b(sm.bias, p.bs, 128);
    __syncthreads();
    layer8<64, 128, 3>(sm.A, sm.wbuf, sm.bias, nullptr, g_tbl_scale, q0);
    __syncthreads();
    stage_w(sm.wbuf, p.Wc1, 64 * 128); stage_b(sm.bias, p.bc1, 128);
    __syncthreads();
    layer8<64, 128, 2>(sm.A, sm.wbuf, sm.bias, sm.Bb, nullptr, 0);
    __syncthreads();
    stage_w(sm.wbuf, p.Wc2, 128 * 128); stage_b(sm.bias, p.bc2, 128);
    __syncthreads();
    layer8<128, 128, 2>(sm.Bb, sm.wbuf, sm.bias, sm.A, nullptr, 0);
    __syncthreads();
    stage_w(sm.wbuf, p.Wc3, 128 * 32); stage_b(sm.bias, p.bc3, 32);
    __syncthreads();
    layer8<128, 32, 2>(sm.A, sm.wbuf, sm.bias, sm.Bb, nullptr, 0);
    __syncthreads();
    if (tid < 8) {
      float s = *p.bc4;
      #pragma unroll
      for (int k = 0; k < 32; k++) s = fmaf(sm.Bb[tid][k], p.Wc4[k], s);
      g_tbl_crit[q0 + tid] = s;
    }
  }
}

// ==================== gather kernel: tables -> outputs =======================
__global__ void __launch_bounds__(NT) acsq_gather(Params p)
{
  __shared__ int   codes[NT];
  __shared__ float red[8];
  const int tid = threadIdx.x;
  const size_t row0 = (size_t)blockIdx.x * NT;
  const size_t b = row0 + tid;

  float lp = 0.f;
  int code = 0;
  if (b < (size_t)p.B) {
    const int o = p.obs[b];
    code = g_idx_cls[o];
    lp = g_loss_cls[o];
    p.out_idx[b]    = (float)code;
    p.out_critic[b] = g_tbl_crit[code];
  }
  codes[tid] = code;

  #pragma unroll
  for (int o = 16; o; o >>= 1) lp += __shfl_down_sync(0xffffffffu, lp, o);
  if ((tid & 31) == 0) red[tid >> 5] = lp;
  __syncthreads();
  if (tid == 0) {
    float t = 0.f;
    #pragma unroll
    for (int w = 0; w < 8; w++) t += red[w];
    g_partials[blockIdx.x] = t;
  }

  float4* oa = reinterpret_cast<float4*>(p.out_actor);
  float4* os = reinterpret_cast<float4*>(p.out_scale);
  const float4* ta = reinterpret_cast<const float4*>(g_tbl_actor);
  const float4* ts = reinterpret_cast<const float4*>(g_tbl_scale);
  for (int i = tid; i < NT * 32; i += NT) {
    const int r = i >> 5, cc = i & 31;
    if (row0 + r < (size_t)p.B) {
      const int cd = codes[r];
      oa[(row0 + r) * 32 + cc] = ta[cd * 32 + cc];
      os[(row0 + r) * 32 + cc] = ts[cd * 32 + cc];
    }
  }
}

__global__ void acsq_reduce(float* out_loss, int nblocks, float scale)
{
  __shared__ float s[NT];
  float v = 0.f;
  for (int i = threadIdx.x; i < nblocks; i += NT) v += g_partials[i];  // fixed order
  s[threadIdx.x] = v;
  __syncthreads();
  for (int o = NT / 2; o > 0; o >>= 1) {
    if (threadIdx.x < o) s[threadIdx.x] += s[threadIdx.x + o];
    __syncthreads();
  }
  if (threadIdx.x == 0) *out_loss = s[0] * scale;
}

extern "C" void kernel_launch(void* const* d_in, const int* in_sizes, int n_in,
                              void* d_out, int out_size)
{
  Params p;
  p.obs      = (const int*)d_in[0];
  p.embed    = (const float*)d_in[1];
  p.W1  = (const float*)d_in[2];  p.b1  = (const float*)d_in[3];
  p.W2  = (const float*)d_in[4];  p.b2  = (const float*)d_in[5];
  p.W3  = (const float*)d_in[6];  p.b3  = (const float*)d_in[7];
  p.Wp  = (const float*)d_in[8];  p.bp  = (const float*)d_in[9];
  p.codebook = (const float*)d_in[10];
  p.Wa  = (const float*)d_in[11]; p.ba  = (const float*)d_in[12];
  p.Ws  = (const float*)d_in[13]; p.bs  = (const float*)d_in[14];
  p.Wc1 = (const float*)d_in[15]; p.bc1 = (const float*)d_in[16];
  p.Wc2 = (const float*)d_in[17]; p.bc2 = (const float*)d_in[18];
  p.Wc3 = (const float*)d_in[19]; p.bc3 = (const float*)d_in[20];
  p.Wc4 = (const float*)d_in[21]; p.bc4 = (const float*)d_in[22];

  const int B   = in_sizes[0];
  const int NC  = in_sizes[1] / 128;   // embed is [NC, 128]
  const int VQN = in_sizes[10] / 64;   // codebook is [VQN, 64]
  p.B = B; p.NC = NC; p.VQN = VQN;
  p.nClsBlk = (NC + 7) / 8;

  float* out = (float*)d_out;
  p.out_actor  = out;                                  // [B,128]
  p.out_scale  = out + (size_t)B * 128;                // [B,128]
  p.out_critic = out + (size_t)2 * B * 128;            // [B]
  p.out_loss   = out + (size_t)2 * B * 128 + B;        // scalar
  p.out_idx    = out + (size_t)2 * B * 128 + B + 1;    // [B] as float

  const int headBlk = (VQN + 7) / 8;
  const int smem = (int)sizeof(SmemAB);
  cudaFuncSetAttribute(acsq_ab, cudaFuncAttributeMaxDynamicSharedMemorySize, smem);
  acsq_ab<<<p.nClsBlk + headBlk, NT, smem>>>(p);

  const int gblocks = (B + NT - 1) / NT;
  acsq_gather<<<gblocks, NT>>>(p);
  acsq_reduce<<<1, NT>>>(p.out_loss, gblocks, 1.25f / ((float)B * 64.f));
}

// round 3
// speedup vs baseline: 21.5818x; 1.7540x over previous
#include <cuda_runtime.h>
#include <math.h>

#define NT 256

struct Params {
  const int*   obs;
  const float *embed, *W1, *b1, *W2, *b2, *W3, *b3, *Wp, *bp, *codebook;
  const float *Wa, *ba, *Ws, *bs, *Wc1, *bc1, *Wc2, *bc2, *Wc3, *bc3, *Wc4, *bc4;
  float *out_actor, *out_scale, *out_critic, *out_loss, *out_idx;
  int NC, VQN, nClsBlk, B, gblocks;
};

// Device-global scratch (no allocation allowed)
__device__ int      g_idx_cls[1024];
__device__ float    g_loss_cls[1024];
__device__ float    g_tbl_actor[512 * 128];
__device__ float    g_tbl_scale[512 * 128];
__device__ float    g_tbl_crit[512];
__device__ float    g_partials[1024];
__device__ unsigned g_ticket;

struct SmemAB {
  float wbuf[2][16384];   // 128 KB: double-buffered weights
  float A[8][128];        // 4 KB
  float Bb[8][128];       // 4 KB
  float part[8][128];     // 4 KB: k-half partial sums
  float dist[8][512];     // 16 KB
  float znorm[8];
};                        // ~156 KB

__device__ __forceinline__ float sigf(float x) { return 1.0f / (1.0f + expf(-x)); }

// ---------------- cp.async helpers ----------------
__device__ __forceinline__ void cpa16(void* sdst, const void* gsrc) {
  unsigned s = (unsigned)__cvta_generic_to_shared(sdst);
  asm volatile("cp.async.cg.shared.global [%0], [%1], 16;\n" :: "r"(s), "l"(gsrc));
}
__device__ __forceinline__ void cpa_commit() { asm volatile("cp.async.commit_group;\n"); }
__device__ __forceinline__ void cpa_wait0()  { asm volatile("cp.async.wait_group 0;\n"); }

__device__ __forceinline__ void pf(float* dst, const float* src, int nfloats) {
  const int n4 = nfloats >> 2;
  for (int i = threadIdx.x; i < n4; i += NT)
    cpa16(reinterpret_cast<float4*>(dst) + i, reinterpret_cast<const float4*>(src) + i);
  cpa_commit();
}

// ---------------- 8-row GEMM layer, 2-row x k-half warp tiling ----------------
// warp w: rowpair rp = w&3 (rows 2rp,2rp+1), khalf kh = w>>2.
// lane = float4 column group (N/4 groups; lanes >= N/4 idle).
// ACT: 0 linear, 1 relu, 2 sigmoid, 3 sigmoid+1e-8
template<int K, int N, int ACT>
__device__ __forceinline__ void layer2(const float (*__restrict__ in)[128],
                                       const float* __restrict__ wb,
                                       const float* __restrict__ bias_g,
                                       float (*__restrict__ outs)[128],
                                       float* __restrict__ outg, int grow0,
                                       SmemAB& sm)
{
  const int tid = threadIdx.x, warp = tid >> 5, lane = tid & 31;
  const int rp = warp & 3, kh = warp >> 2;
  const int r0 = rp * 2;
  constexpr int NG = N / 4;
  const bool active = lane < NG;

  float4 acc0 = make_float4(0.f, 0.f, 0.f, 0.f);
  float4 acc1 = make_float4(0.f, 0.f, 0.f, 0.f);

  if (active) {
    const float4* w4 = reinterpret_cast<const float4*>(wb) + lane;
    const int kbeg = kh * (K / 2), kend = kbeg + (K / 2);
    #pragma unroll 4
    for (int k = kbeg; k < kend; k += 4) {
      const float4 a0 = *reinterpret_cast<const float4*>(&in[r0][k]);     // broadcast
      const float4 a1 = *reinterpret_cast<const float4*>(&in[r0 + 1][k]); // broadcast
      #pragma unroll
      for (int j = 0; j < 4; j++) {
        const float4 w = w4[(size_t)(k + j) * NG];
        const float aj0 = j == 0 ? a0.x : j == 1 ? a0.y : j == 2 ? a0.z : a0.w;
        const float aj1 = j == 0 ? a1.x : j == 1 ? a1.y : j == 2 ? a1.z : a1.w;
        acc0.x = fmaf(aj0, w.x, acc0.x); acc0.y = fmaf(aj0, w.y, acc0.y);
        acc0.z = fmaf(aj0, w.z, acc0.z); acc0.w = fmaf(aj0, w.w, acc0.w);
        acc1.x = fmaf(aj1, w.x, acc1.x); acc1.y = fmaf(aj1, w.y, acc1.y);
        acc1.z = fmaf(aj1, w.z, acc1.z); acc1.w = fmaf(aj1, w.w, acc1.w);
      }
    }
  }
  if (kh == 1 && active) {
    *reinterpret_cast<float4*>(&sm.part[r0][lane * 4])     = acc0;
    *reinterpret_cast<float4*>(&sm.part[r0 + 1][lane * 4]) = acc1;
  }
  __syncthreads();
  if (kh == 0 && active) {
    const float4 p0 = *reinterpret_cast<const float4*>(&sm.part[r0][lane * 4]);
    const float4 p1 = *reinterpret_cast<const float4*>(&sm.part[r0 + 1][lane * 4]);
    const float4 bb = __ldg(reinterpret_cast<const float4*>(bias_g) + lane);
    float v0[4] = {acc0.x + p0.x + bb.x, acc0.y + p0.y + bb.y,
                   acc0.z + p0.z + bb.z, acc0.w + p0.w + bb.w};
    float v1[4] = {acc1.x + p1.x + bb.x, acc1.y + p1.y + bb.y,
                   acc1.z + p1.z + bb.z, acc1.w + p1.w + bb.w};
    #pragma unroll
    for (int j = 0; j < 4; j++) {
      if (ACT == 1) { v0[j] = v0[j] > 0.f ? v0[j] : 0.f; v1[j] = v1[j] > 0.f ? v1[j] : 0.f; }
      if (ACT == 2 || ACT == 3) { v0[j] = sigf(v0[j]); v1[j] = sigf(v1[j]); }
      if (ACT == 3) { v0[j] += 1e-8f; v1[j] += 1e-8f; }
    }
    const float4 o0 = make_float4(v0[0], v0[1], v0[2], v0[3]);
    const float4 o1 = make_float4(v1[0], v1[1], v1[2], v1[3]);
    if (outs) {
      *reinterpret_cast<float4*>(&outs[r0][lane * 4])     = o0;
      *reinterpret_cast<float4*>(&outs[r0 + 1][lane * 4]) = o1;
    }
    if (outg) {
      reinterpret_cast<float4*>(outg)[(size_t)(grow0 + r0) * NG + lane]     = o0;
      reinterpret_cast<float4*>(outg)[(size_t)(grow0 + r0 + 1) * NG + lane] = o1;
    }
  }
  __syncthreads();
}

__global__ void __launch_bounds__(NT, 1) acsq_ab(Params p)
{
  extern __shared__ char smraw[];
  SmemAB& sm = *reinterpret_cast<SmemAB*>(smraw);
  const int tid = threadIdx.x;

  if ((int)blockIdx.x < p.nClsBlk) {
    // ================= CLASS PATH =================
    const int c0 = blockIdx.x * 8;

    pf(sm.wbuf[0], p.W1, 128 * 128);
    {   // embed gather: 8 rows x 32 float4, one per thread
      const int r = tid >> 5, col = tid & 31, cls = c0 + r;
      float4 v = make_float4(0.f, 0.f, 0.f, 0.f);
      if (cls < p.NC)
        v = __ldg(reinterpret_cast<const float4*>(p.embed + (size_t)cls * 128) + col);
      reinterpret_cast<float4*>(sm.A[r])[col] = v;
    }
    cpa_wait0(); __syncthreads();

    pf(sm.wbuf[1], p.W2, 128 * 128);
    layer2<128, 128, 1>(sm.A, sm.wbuf[0], p.b1, sm.Bb, nullptr, 0, sm);
    cpa_wait0(); __syncthreads();

    pf(sm.wbuf[0], p.W3, 128 * 128);
    layer2<128, 128, 1>(sm.Bb, sm.wbuf[1], p.b2, sm.A, nullptr, 0, sm);
    cpa_wait0(); __syncthreads();

    pf(sm.wbuf[1], p.Wp, 128 * 64);
    layer2<128, 128, 1>(sm.A, sm.wbuf[0], p.b3, sm.Bb, nullptr, 0, sm);
    cpa_wait0(); __syncthreads();

    layer2<128, 64, 0>(sm.Bb, sm.wbuf[1], p.bp, sm.A, nullptr, 0, sm);
    // z in A[:,0:64]
    if (tid < 8) {
      float s = 0.f;
      #pragma unroll
      for (int k = 0; k < 64; k++) s = fmaf(sm.A[tid][k], sm.A[tid][k], s);
      sm.znorm[tid] = s;
    }
    __syncthreads();

    // ---- VQ distances: thread per code (2 codes/thread), code row in regs ----
    const float4* A4[8];
    #pragma unroll
    for (int r = 0; r < 8; r++) A4[r] = reinterpret_cast<const float4*>(sm.A[r]);
    #pragma unroll
    for (int h = 0; h < 2; h++) {
      const int cc = h * 256 + tid;
      if (cc < p.VQN) {
        float4 cb[16];
        const float4* cp = reinterpret_cast<const float4*>(p.codebook + (size_t)cc * 64);
        #pragma unroll
        for (int q = 0; q < 16; q++) cb[q] = __ldg(cp + q);
        float cn = 0.f;
        #pragma unroll
        for (int q = 0; q < 16; q++) {
          cn = fmaf(cb[q].x, cb[q].x, cn); cn = fmaf(cb[q].y, cb[q].y, cn);
          cn = fmaf(cb[q].z, cb[q].z, cn); cn = fmaf(cb[q].w, cb[q].w, cn);
        }
        #pragma unroll
        for (int r = 0; r < 8; r++) {
          float dot = 0.f;
          #pragma unroll
          for (int q = 0; q < 16; q++) {
            const float4 a = A4[r][q];            // broadcast LDS.128
            dot = fmaf(a.x, cb[q].x, dot); dot = fmaf(a.y, cb[q].y, dot);
            dot = fmaf(a.z, cb[q].z, dot); dot = fmaf(a.w, cb[q].w, dot);
          }
          sm.dist[r][cc] = sm.znorm[r] - 2.f * dot + cn;
        }
      }
    }
    __syncthreads();

    // ---- argmin per row (warp r), lexicographic (d, idx) ----
    const int warp = tid >> 5, lane = tid & 31;
    {
      const int r = warp;
      float best = 3.4e38f; int bi = 0;
      for (int cc = lane; cc < p.VQN; cc += 32) {
        const float d = sm.dist[r][cc];
        if (d < best) { best = d; bi = cc; }
      }
      #pragma unroll
      for (int o = 16; o; o >>= 1) {
        const float ob = __shfl_down_sync(0xffffffffu, best, o);
        const int   oi = __shfl_down_sync(0xffffffffu, bi,   o);
        if (ob < best || (ob == best && oi < bi)) { best = ob; bi = oi; }
      }
      bi = __shfl_sync(0xffffffffu, bi, 0);
      float ls = 0.f;
      for (int k = lane; k < 64; k += 32) {
        const float dq = __ldg(p.codebook + (size_t)bi * 64 + k) - sm.A[r][k];
        ls = fmaf(dq, dq, ls);
      }
      #pragma unroll
      for (int o = 16; o; o >>= 1) ls += __shfl_down_sync(0xffffffffu, ls, o);
      if (lane == 0 && c0 + r < p.NC) {
        g_idx_cls[c0 + r]  = bi;
        g_loss_cls[c0 + r] = ls;
      }
    }
  } else {
    // ================= HEAD PATH =================
    const int q0 = (blockIdx.x - p.nClsBlk) * 8;

    pf(sm.wbuf[0], p.Wa, 64 * 128);
    if (tid < 8 * 16) {     // gather 8 codebook rows (64 floats each)
      const int r = tid >> 4, col = tid & 15;
      reinterpret_cast<float4*>(sm.A[r])[col] =
          __ldg(reinterpret_cast<const float4*>(p.codebook + (size_t)(q0 + r) * 64) + col);
    }
    cpa_wait0(); __syncthreads();

    pf(sm.wbuf[1], p.Ws, 64 * 128);
    layer2<64, 128, 2>(sm.A, sm.wbuf[0], p.ba, nullptr, g_tbl_actor, q0, sm);
    cpa_wait0(); __syncthreads();

    pf(sm.wbuf[0], p.Wc1, 64 * 128);
    layer2<64, 128, 3>(sm.A, sm.wbuf[1], p.bs, nullptr, g_tbl_scale, q0, sm);
    cpa_wait0(); __syncthreads();

    pf(sm.wbuf[1], p.Wc2, 128 * 128);
    layer2<64, 128, 2>(sm.A, sm.wbuf[0], p.bc1, sm.Bb, nullptr, 0, sm);
    cpa_wait0(); __syncthreads();

    pf(sm.wbuf[0], p.Wc3, 128 * 32);
    layer2<128, 128, 2>(sm.Bb, sm.wbuf[1], p.bc2, sm.A, nullptr, 0, sm);
    cpa_wait0(); __syncthreads();

    layer2<128, 32, 2>(sm.A, sm.wbuf[0], p.bc3, sm.Bb, nullptr, 0, sm);

    if (tid < 8) {
      float s = __ldg(p.bc4);
      #pragma unroll
      for (int k = 0; k < 32; k++) s = fmaf(sm.Bb[tid][k], __ldg(p.Wc4 + k), s);
      g_tbl_crit[q0 + tid] = s;
    }
  }
}

// ==================== gather kernel + fused final loss reduce ================
__global__ void __launch_bounds__(NT) acsq_gather(Params p, float scale)
{
  __shared__ int   codes[NT];
  __shared__ float red[8];
  __shared__ float s[NT];
  __shared__ bool  lastblk;
  const int tid = threadIdx.x;
  const size_t row0 = (size_t)blockIdx.x * NT;
  const size_t b = row0 + tid;

  float lp = 0.f;
  int code = 0;
  if (b < (size_t)p.B) {
    const int o = p.obs[b];
    code = g_idx_cls[o];
    lp = g_loss_cls[o];
    p.out_idx[b]    = (float)code;
    p.out_critic[b] = g_tbl_crit[code];
  }
  codes[tid] = code;

  #pragma unroll
  for (int o = 16; o; o >>= 1) lp += __shfl_down_sync(0xffffffffu, lp, o);
  if ((tid & 31) == 0) red[tid >> 5] = lp;
  __syncthreads();
  if (tid == 0) {
    float t = 0.f;
    #pragma unroll
    for (int w = 0; w < 8; w++) t += red[w];
    g_partials[blockIdx.x] = t;
    __threadfence();
    lastblk = (atomicAdd(&g_ticket, 1u) == (unsigned)(gridDim.x - 1));
  }

  const float4* ta = reinterpret_cast<const float4*>(g_tbl_actor);
  const float4* ts = reinterpret_cast<const float4*>(g_tbl_scale);
  float4* oa = reinterpret_cast<float4*>(p.out_actor);
  float4* os = reinterpret_cast<float4*>(p.out_scale);
  __syncthreads();
  for (int i = tid; i < NT * 32; i += NT) {
    const int r = i >> 5, cc = i & 31;
    if (row0 + r < (size_t)p.B) {
      const int cd = codes[r];
      oa[(row0 + r) * 32 + cc] = ta[cd * 32 + cc];
      os[(row0 + r) * 32 + cc] = ts[cd * 32 + cc];
    }
  }

  if (lastblk) {
    float v = 0.f;
    for (int i = tid; i < p.gblocks; i += NT) v += g_partials[i];  // fixed order
    s[tid] = v;
    __syncthreads();
    for (int o = NT / 2; o > 0; o >>= 1) {
      if (tid < o) s[tid] += s[tid + o];
      __syncthreads();
    }
    if (tid == 0) { *p.out_loss = s[0] * scale; g_ticket = 0u; }
  }
}

extern "C" void kernel_launch(void* const* d_in, const int* in_sizes, int n_in,
                              void* d_out, int out_size)
{
  Params p;
  p.obs      = (const int*)d_in[0];
  p.embed    = (const float*)d_in[1];
  p.W1  = (const float*)d_in[2];  p.b1  = (const float*)d_in[3];
  p.W2  = (const float*)d_in[4];  p.b2  = (const float*)d_in[5];
  p.W3  = (const float*)d_in[6];  p.b3  = (const float*)d_in[7];
  p.Wp  = (const float*)d_in[8];  p.bp  = (const float*)d_in[9];
  p.codebook = (const float*)d_in[10];
  p.Wa  = (const float*)d_in[11]; p.ba  = (const float*)d_in[12];
  p.Ws  = (const float*)d_in[13]; p.bs  = (const float*)d_in[14];
  p.Wc1 = (const float*)d_in[15]; p.bc1 = (const float*)d_in[16];
  p.Wc2 = (const float*)d_in[17]; p.bc2 = (const float*)d_in[18];
  p.Wc3 = (const float*)d_in[19]; p.bc3 = (const float*)d_in[20];
  p.Wc4 = (const float*)d_in[21]; p.bc4 = (const float*)d_in[22];

  const int B   = in_sizes[0];
  const int NC  = in_sizes[1] / 128;   // embed is [NC, 128]
  const int VQN = in_sizes[10] / 64;   // codebook is [VQN, 64]
  p.B = B; p.NC = NC; p.VQN = VQN;
  p.nClsBlk = (NC + 7) / 8;
  p.gblocks = (B + NT - 1) / NT;

  float* out = (float*)d_out;
  p.out_actor  = out;                                  // [B,128]
  p.out_scale  = out + (size_t)B * 128;                // [B,128]
  p.out_critic = out + (size_t)2 * B * 128;            // [B]
  p.out_loss   = out + (size_t)2 * B * 128 + B;        // scalar
  p.out_idx    = out + (size_t)2 * B * 128 + B + 1;    // [B] as float

  const int headBlk = (VQN + 7) / 8;
  const int smem = (int)sizeof(SmemAB);
  cudaFuncSetAttribute(acsq_ab, cudaFuncAttributeMaxDynamicSharedMemorySize, smem);
  acsq_ab<<<p.nClsBlk + headBlk, NT, smem>>>(p);
  acsq_gather<<<p.gblocks, NT>>>(p, 1.25f / ((float)B * 64.f));
}

// round 4
// speedup vs baseline: 22.9925x; 1.0654x over previous
#include <cuda_runtime.h>
#include <math.h>

#define NTA 512   // ab kernel threads
#define NTG 256   // gather kernel threads
#define RB  16    // rows (classes/codes) per ab block

struct Params {
  const int*   obs;
  const float *embed, *W1, *b1, *W2, *b2, *W3, *b3, *Wp, *bp, *codebook;
  const float *Wa, *ba, *Ws, *bs, *Wc1, *bc1, *Wc2, *bc2, *Wc3, *bc3, *Wc4, *bc4;
  float *out_actor, *out_scale, *out_critic, *out_loss, *out_idx;
  int NC, VQN, nClsBlk, B, gblocks;
};

// Device-global scratch (no allocation allowed)
__device__ int      g_idx_cls[1024];
__device__ float    g_loss_cls[1024];
__device__ float    g_tbl_actor[512 * 128];
__device__ float    g_tbl_scale[512 * 128];
__device__ float    g_tbl_crit[512];
__device__ float    g_partials[1024];
__device__ unsigned g_ticket;

struct SmemAB {
  float wbuf[2][16384];     // 128 KB: double-buffered weights
  float A[RB][128];         // 8 KB
  float Bb[RB][128];        // 8 KB
  float part[RB][128];      // 8 KB: k-half partials
  float dist[RB][512];      // 32 KB
  float znorm[RB];
};                          // ~184 KB

__device__ __forceinline__ float sigf(float x) { return 1.0f / (1.0f + expf(-x)); }

// ---------------- cp.async helpers ----------------
__device__ __forceinline__ void cpa16(void* sdst, const void* gsrc) {
  unsigned s = (unsigned)__cvta_generic_to_shared(sdst);
  asm volatile("cp.async.cg.shared.global [%0], [%1], 16;\n" :: "r"(s), "l"(gsrc));
}
__device__ __forceinline__ void cpa_commit() { asm volatile("cp.async.commit_group;\n"); }
__device__ __forceinline__ void cpa_wait0()  { asm volatile("cp.async.wait_group 0;\n"); }

__device__ __forceinline__ void pf(float* dst, const float* src, int nfloats) {
  const int n4 = nfloats >> 2;
  for (int i = threadIdx.x; i < n4; i += NTA)
    cpa16(reinterpret_cast<float4*>(dst) + i, reinterpret_cast<const float4*>(src) + i);
  cpa_commit();
}

// ------------- RB-row GEMM layer, 2-row x k-half warp tiling -------------
// warp w (16 warps): rowpair rp = w&7 (rows 2rp,2rp+1), khalf kh = w>>3.
// lane = float4 column group (N/4 groups; lanes >= N/4 idle for N<128).
// ACT: 0 linear, 1 relu, 2 sigmoid, 3 sigmoid+1e-8
template<int K, int N, int ACT>
__device__ __forceinline__ void layerX(const float (*__restrict__ in)[128],
                                       const float* __restrict__ wb,
                                       const float* __restrict__ bias_g,
                                       float (*__restrict__ outs)[128],
                                       float* __restrict__ outg, int grow0,
                                       SmemAB& sm)
{
  const int tid = threadIdx.x, warp = tid >> 5, lane = tid & 31;
  const int rp = warp & 7, kh = warp >> 3;
  const int r0 = rp * 2;
  constexpr int NG = N / 4;
  const bool active = lane < NG;

  float4 acc0 = make_float4(0.f, 0.f, 0.f, 0.f);
  float4 acc1 = make_float4(0.f, 0.f, 0.f, 0.f);

  if (active) {
    const float4* w4 = reinterpret_cast<const float4*>(wb) + lane;
    const int kbeg = kh * (K / 2), kend = kbeg + (K / 2);
    #pragma unroll 4
    for (int k = kbeg; k < kend; k += 4) {
      const float4 a0 = *reinterpret_cast<const float4*>(&in[r0][k]);     // broadcast
      const float4 a1 = *reinterpret_cast<const float4*>(&in[r0 + 1][k]); // broadcast
      #pragma unroll
      for (int j = 0; j < 4; j++) {
        const float4 w = w4[(size_t)(k + j) * NG];
        const float aj0 = j == 0 ? a0.x : j == 1 ? a0.y : j == 2 ? a0.z : a0.w;
        const float aj1 = j == 0 ? a1.x : j == 1 ? a1.y : j == 2 ? a1.z : a1.w;
        acc0.x = fmaf(aj0, w.x, acc0.x); acc0.y = fmaf(aj0, w.y, acc0.y);
        acc0.z = fmaf(aj0, w.z, acc0.z); acc0.w = fmaf(aj0, w.w, acc0.w);
        acc1.x = fmaf(aj1, w.x, acc1.x); acc1.y = fmaf(aj1, w.y, acc1.y);
        acc1.z = fmaf(aj1, w.z, acc1.z); acc1.w = fmaf(aj1, w.w, acc1.w);
      }
    }
  }
  if (kh == 1 && active) {
    *reinterpret_cast<float4*>(&sm.part[r0][lane * 4])     = acc0;
    *reinterpret_cast<float4*>(&sm.part[r0 + 1][lane * 4]) = acc1;
  }
  __syncthreads();
  if (kh == 0 && active) {
    const float4 p0 = *reinterpret_cast<const float4*>(&sm.part[r0][lane * 4]);
    const float4 p1 = *reinterpret_cast<const float4*>(&sm.part[r0 + 1][lane * 4]);
    const float4 bb = __ldg(reinterpret_cast<const float4*>(bias_g) + lane);
    float v0[4] = {acc0.x + p0.x + bb.x, acc0.y + p0.y + bb.y,
                   acc0.z + p0.z + bb.z, acc0.w + p0.w + bb.w};
    float v1[4] = {acc1.x + p1.x + bb.x, acc1.y + p1.y + bb.y,
                   acc1.z + p1.z + bb.z, acc1.w + p1.w + bb.w};
    #pragma unroll
    for (int j = 0; j < 4; j++) {
      if (ACT == 1) { v0[j] = v0[j] > 0.f ? v0[j] : 0.f; v1[j] = v1[j] > 0.f ? v1[j] : 0.f; }
      if (ACT == 2 || ACT == 3) { v0[j] = sigf(v0[j]); v1[j] = sigf(v1[j]); }
      if (ACT == 3) { v0[j] += 1e-8f; v1[j] += 1e-8f; }
    }
    const float4 o0 = make_float4(v0[0], v0[1], v0[2], v0[3]);
    const float4 o1 = make_float4(v1[0], v1[1], v1[2], v1[3]);
    if (outs) {
      *reinterpret_cast<float4*>(&outs[r0][lane * 4])     = o0;
      *reinterpret_cast<float4*>(&outs[r0 + 1][lane * 4]) = o1;
    }
    if (outg) {
      reinterpret_cast<float4*>(outg)[(size_t)(grow0 + r0) * NG + lane]     = o0;
      reinterpret_cast<float4*>(outg)[(size_t)(grow0 + r0 + 1) * NG + lane] = o1;
    }
  }
  __syncthreads();
}

__global__ void __launch_bounds__(NTA, 1) acsq_ab(Params p)
{
  extern __shared__ char smraw[];
  SmemAB& sm = *reinterpret_cast<SmemAB*>(smraw);
  const int tid = threadIdx.x;

  if ((int)blockIdx.x < p.nClsBlk) {
    // ================= CLASS PATH: 16 classes =================
    const int c0 = blockIdx.x * RB;

    pf(sm.wbuf[0], p.W1, 128 * 128);
    {   // embed gather: 16 rows x 32 float4, one per thread
      const int r = tid >> 5, col = tid & 31, cls = c0 + r;
      float4 v = make_float4(0.f, 0.f, 0.f, 0.f);
      if (cls < p.NC)
        v = __ldg(reinterpret_cast<const float4*>(p.embed + (size_t)cls * 128) + col);
      reinterpret_cast<float4*>(sm.A[r])[col] = v;
    }
    cpa_wait0(); __syncthreads();

    pf(sm.wbuf[1], p.W2, 128 * 128);
    layerX<128, 128, 1>(sm.A, sm.wbuf[0], p.b1, sm.Bb, nullptr, 0, sm);
    cpa_wait0(); __syncthreads();

    pf(sm.wbuf[0], p.W3, 128 * 128);
    layerX<128, 128, 1>(sm.Bb, sm.wbuf[1], p.b2, sm.A, nullptr, 0, sm);
    cpa_wait0(); __syncthreads();

    pf(sm.wbuf[1], p.Wp, 128 * 64);
    layerX<128, 128, 1>(sm.A, sm.wbuf[0], p.b3, sm.Bb, nullptr, 0, sm);
    cpa_wait0(); __syncthreads();

    layerX<128, 64, 0>(sm.Bb, sm.wbuf[1], p.bp, sm.A, nullptr, 0, sm);
    // z in A[:,0:64]
    if (tid < RB) {
      float s = 0.f;
      #pragma unroll
      for (int k = 0; k < 64; k++) s = fmaf(sm.A[tid][k], sm.A[tid][k], s);
      sm.znorm[tid] = s;
    }
    __syncthreads();

    // ---- VQ distances: one thread per code (512 threads = 512 codes) ----
    {
      const int cc = tid;
      if (cc < p.VQN) {
        float4 cb[16];
        const float4* cp = reinterpret_cast<const float4*>(p.codebook + (size_t)cc * 64);
        #pragma unroll
        for (int q = 0; q < 16; q++) cb[q] = __ldg(cp + q);
        float cn = 0.f;
        #pragma unroll
        for (int q = 0; q < 16; q++) {
          cn = fmaf(cb[q].x, cb[q].x, cn); cn = fmaf(cb[q].y, cb[q].y, cn);
          cn = fmaf(cb[q].z, cb[q].z, cn); cn = fmaf(cb[q].w, cb[q].w, cn);
        }
        #pragma unroll
        for (int r = 0; r < RB; r++) {
          const float4* A4 = reinterpret_cast<const float4*>(sm.A[r]);
          float dot = 0.f;
          #pragma unroll
          for (int q = 0; q < 16; q++) {
            const float4 a = A4[q];               // broadcast LDS.128
            dot = fmaf(a.x, cb[q].x, dot); dot = fmaf(a.y, cb[q].y, dot);
            dot = fmaf(a.z, cb[q].z, dot); dot = fmaf(a.w, cb[q].w, dot);
          }
          sm.dist[r][cc] = sm.znorm[r] - 2.f * dot + cn;
        }
      }
    }
    __syncthreads();

    // ---- argmin per row (warp r of 16), lexicographic (d, idx) ----
    const int warp = tid >> 5, lane = tid & 31;
    {
      const int r = warp;
      float best = 3.4e38f; int bi = 0;
      for (int cc = lane; cc < p.VQN; cc += 32) {
        const float d = sm.dist[r][cc];
        if (d < best) { best = d; bi = cc; }
      }
      #pragma unroll
      for (int o = 16; o; o >>= 1) {
        const float ob = __shfl_down_sync(0xffffffffu, best, o);
        const int   oi = __shfl_down_sync(0xffffffffu, bi,   o);
        if (ob < best || (ob == best && oi < bi)) { best = ob; bi = oi; }
      }
      bi = __shfl_sync(0xffffffffu, bi, 0);
      float ls = 0.f;
      for (int k = lane; k < 64; k += 32) {
        const float dq = __ldg(p.codebook + (size_t)bi * 64 + k) - sm.A[r][k];
        ls = fmaf(dq, dq, ls);
      }
      #pragma unroll
      for (int o = 16; o; o >>= 1) ls += __shfl_down_sync(0xffffffffu, ls, o);
      if (lane == 0 && c0 + r < p.NC) {
        g_idx_cls[c0 + r]  = bi;
        g_loss_cls[c0 + r] = ls;
      }
    }
  } else {
    // ================= HEAD PATH: 16 codes =================
    const int q0 = (blockIdx.x - p.nClsBlk) * RB;

    pf(sm.wbuf[0], p.Wa, 64 * 128);
    if (tid < RB * 16) {     // gather 16 codebook rows (64 floats each)
      const int r = tid >> 4, col = tid & 15;
      reinterpret_cast<float4*>(sm.A[r])[col] =
          __ldg(reinterpret_cast<const float4*>(p.codebook + (size_t)(q0 + r) * 64) + col);
    }
    cpa_wait0(); __syncthreads();

    pf(sm.wbuf[1], p.Ws, 64 * 128);
    layerX<64, 128, 2>(sm.A, sm.wbuf[0], p.ba, nullptr, g_tbl_actor, q0, sm);
    cpa_wait0(); __syncthreads();

    pf(sm.wbuf[0], p.Wc1, 64 * 128);
    layerX<64, 128, 3>(sm.A, sm.wbuf[1], p.bs, nullptr, g_tbl_scale, q0, sm);
    cpa_wait0(); __syncthreads();

    pf(sm.wbuf[1], p.Wc2, 128 * 128);
    layerX<64, 128, 2>(sm.A, sm.wbuf[0], p.bc1, sm.Bb, nullptr, 0, sm);
    cpa_wait0(); __syncthreads();

    pf(sm.wbuf[0], p.Wc3, 128 * 32);
    layerX<128, 128, 2>(sm.Bb, sm.wbuf[1], p.bc2, sm.A, nullptr, 0, sm);
    cpa_wait0(); __syncthreads();

    layerX<128, 32, 2>(sm.A, sm.wbuf[0], p.bc3, sm.Bb, nullptr, 0, sm);

    if (tid < RB) {
      float s = __ldg(p.bc4);
      #pragma unroll
      for (int k = 0; k < 32; k++) s = fmaf(sm.Bb[tid][k], __ldg(p.Wc4 + k), s);
      g_tbl_crit[q0 + tid] = s;
    }
  }
}

// ==================== gather kernel + fused final loss reduce ================
__global__ void __launch_bounds__(NTG) acsq_gather(Params p, float scale)
{
  __shared__ int   codes[NTG];
  __shared__ float red[8];
  __shared__ float s[NTG];
  __shared__ bool  lastblk;
  const int tid = threadIdx.x;
  const size_t row0 = (size_t)blockIdx.x * NTG;
  const size_t b = row0 + tid;

  float lp = 0.f;
  int code = 0;
  if (b < (size_t)p.B) {
    const int o = p.obs[b];
    code = g_idx_cls[o];
    lp = g_loss_cls[o];
    p.out_idx[b]    = (float)code;
    p.out_critic[b] = g_tbl_crit[code];
  }
  codes[tid] = code;

  #pragma unroll
  for (int o = 16; o; o >>= 1) lp += __shfl_down_sync(0xffffffffu, lp, o);
  if ((tid & 31) == 0) red[tid >> 5] = lp;
  __syncthreads();
  if (tid == 0) {
    float t = 0.f;
    #pragma unroll
    for (int w = 0; w < 8; w++) t += red[w];
    g_partials[blockIdx.x] = t;
    __threadfence();
    lastblk = (atomicAdd(&g_ticket, 1u) == (unsigned)(gridDim.x - 1));
  }

  const float4* ta = reinterpret_cast<const float4*>(g_tbl_actor);
  const float4* ts = reinterpret_cast<const float4*>(g_tbl_scale);
  float4* oa = reinterpret_cast<float4*>(p.out_actor);
  float4* os = reinterpret_cast<float4*>(p.out_scale);
  __syncthreads();
  for (int i = tid; i < NTG * 32; i += NTG) {
    const int r = i >> 5, cc = i & 31;
    if (row0 + r < (size_t)p.B) {
      const int cd = codes[r];
      oa[(row0 + r) * 32 + cc] = ta[cd * 32 + cc];
      os[(row0 + r) * 32 + cc] = ts[cd * 32 + cc];
    }
  }

  if (lastblk) {
    float v = 0.f;
    for (int i = tid; i < p.gblocks; i += NTG) v += g_partials[i];  // fixed order
    s[tid] = v;
    __syncthreads();
    for (int o = NTG / 2; o > 0; o >>= 1) {
      if (tid < o) s[tid] += s[tid + o];
      __syncthreads();
    }
    if (tid == 0) { *p.out_loss = s[0] * scale; g_ticket = 0u; }
  }
}

extern "C" void kernel_launch(void* const* d_in, const int* in_sizes, int n_in,
                              void* d_out, int out_size)
{
  Params p;
  p.obs      = (const int*)d_in[0];
  p.embed    = (const float*)d_in[1];
  p.W1  = (const float*)d_in[2];  p.b1  = (const float*)d_in[3];
  p.W2  = (const float*)d_in[4];  p.b2  = (const float*)d_in[5];
  p.W3  = (const float*)d_in[6];  p.b3  = (const float*)d_in[7];
  p.Wp  = (const float*)d_in[8];  p.bp  = (const float*)d_in[9];
  p.codebook = (const float*)d_in[10];
  p.Wa  = (const float*)d_in[11]; p.ba  = (const float*)d_in[12];
  p.Ws  = (const float*)d_in[13]; p.bs  = (const float*)d_in[14];
  p.Wc1 = (const float*)d_in[15]; p.bc1 = (const float*)d_in[16];
  p.Wc2 = (const float*)d_in[17]; p.bc2 = (const float*)d_in[18];
  p.Wc3 = (const float*)d_in[19]; p.bc3 = (const float*)d_in[20];
  p.Wc4 = (const float*)d_in[21]; p.bc4 = (const float*)d_in[22];

  const int B   = in_sizes[0];
  const int NC  = in_sizes[1] / 128;   // embed is [NC, 128]
  const int VQN = in_sizes[10] / 64;   // codebook is [VQN, 64]
  p.B = B; p.NC = NC; p.VQN = VQN;
  p.nClsBlk = (NC + RB - 1) / RB;
  p.gblocks = (B + NTG - 1) / NTG;

  float* out = (float*)d_out;
  p.out_actor  = out;                                  // [B,128]
  p.out_scale  = out + (size_t)B * 128;                // [B,128]
  p.out_critic = out + (size_t)2 * B * 128;            // [B]
  p.out_loss   = out + (size_t)2 * B * 128 + B;        // scalar
  p.out_idx    = out + (size_t)2 * B * 128 + B + 1;    // [B] as float

  const int headBlk = (VQN + RB - 1) / RB;
  const int smem = (int)sizeof(SmemAB);
  cudaFuncSetAttribute(acsq_ab, cudaFuncAttributeMaxDynamicSharedMemorySize, smem);
  acsq_ab<<<p.nClsBlk + headBlk, NTA, smem>>>(p);
  acsq_gather<<<p.gblocks, NTG>>>(p, 1.25f / ((float)B * 64.f));
}